// round 2
// baseline (speedup 1.0000x reference)
#include <cuda_runtime.h>
#include <float.h>
#include <math.h>

#define FULLMASK 0xffffffffu

static const int NN = 20000;   // nodes
static const int NE = 640000;  // edges
static const int NG = 64;      // graphs

// ---------------- scratch (static device allocations; sanctioned) ------------
__device__ float g_XL[20000 * 512];
__device__ float g_XR[20000 * 512];
__device__ float g_HA[20000 * 256];
__device__ float g_HB[20000 * 256];
__device__ int   g_cnt[20000];
__device__ int   g_rowptr[20001];
__device__ int   g_cursor[20000];
__device__ int   g_csrc[640000];
__device__ int   g_ceid[640000];
__device__ int   g_gcnt[64];

// ---------------- CSR build --------------------------------------------------
__global__ void k_zero_cnt(int* cnt, int n) {
    int i = blockIdx.x * blockDim.x + threadIdx.x;
    if (i < n) cnt[i] = 0;
}

__global__ void k_hist(const int* __restrict__ ei, int* cnt, int E) {
    int e = blockIdx.x * blockDim.x + threadIdx.x;
    if (e < E) atomicAdd(&cnt[ei[E + e]], 1);
}

// single-block scan over 20000 counts -> rowptr (inclusive at i+1), cursor = exclusive
__global__ void k_scan(const int* __restrict__ cnt, int* rowptr, int* cursor, int n) {
    __shared__ int sh[1024];
    __shared__ int carry;
    if (threadIdx.x == 0) { carry = 0; rowptr[0] = 0; }
    __syncthreads();
    for (int base = 0; base < n; base += 1024) {
        int i = base + threadIdx.x;
        int v = (i < n) ? cnt[i] : 0;
        sh[threadIdx.x] = v;
        __syncthreads();
        for (int off = 1; off < 1024; off <<= 1) {
            int t = (threadIdx.x >= off) ? sh[threadIdx.x - off] : 0;
            __syncthreads();
            sh[threadIdx.x] += t;
            __syncthreads();
        }
        int incl = sh[threadIdx.x] + carry;
        if (i < n) { rowptr[i + 1] = incl; cursor[i] = incl - v; }
        __syncthreads();
        if (threadIdx.x == 1023) carry = incl;
        __syncthreads();
    }
}

__global__ void k_scatter(const int* __restrict__ ei, int* cursor,
                          int* __restrict__ csrc, int* __restrict__ ceid, int E) {
    int e = blockIdx.x * blockDim.x + threadIdx.x;
    if (e < E) {
        int dst = ei[E + e];
        int p = atomicAdd(&cursor[dst], 1);
        csrc[p] = ei[e];
        ceid[p] = e;
    }
}

// ---------------- fp32 tiled GEMM: C[M,N] = A[M,K] @ B[K,N] + bias -----------
// BM=BN=64, BK=16, 256 threads, 4x4 per thread. N,K multiples required (true here).
__global__ __launch_bounds__(256)
void k_gemm_bias(const float* __restrict__ A, const float* __restrict__ B,
                 const float* __restrict__ bias, float* __restrict__ C,
                 int M, int N, int K)
{
    __shared__ float As[16][68];
    __shared__ float Bs[16][64];
    const int t = threadIdx.x;
    const int m0 = blockIdx.y * 64;
    const int n0 = blockIdx.x * 64;
    const int tx = t & 15, ty = t >> 4;
    const int arow = t >> 2;
    const int acol = (t & 3) * 4;
    const int brow = t >> 4;
    const int bcol = (t & 15) * 4;

    float acc[4][4];
#pragma unroll
    for (int i = 0; i < 4; i++)
#pragma unroll
        for (int j = 0; j < 4; j++) acc[i][j] = 0.f;

    for (int k0 = 0; k0 < K; k0 += 16) {
        float4 av = make_float4(0.f, 0.f, 0.f, 0.f);
        if (m0 + arow < M)
            av = *(const float4*)(A + (long)(m0 + arow) * K + k0 + acol);
        As[acol + 0][arow] = av.x;
        As[acol + 1][arow] = av.y;
        As[acol + 2][arow] = av.z;
        As[acol + 3][arow] = av.w;
        float4 bv = *(const float4*)(B + (long)(k0 + brow) * N + n0 + bcol);
        *(float4*)&Bs[brow][bcol] = bv;
        __syncthreads();
#pragma unroll
        for (int kk = 0; kk < 16; kk++) {
            float4 a = *(const float4*)&As[kk][ty * 4];
            float4 b = *(const float4*)&Bs[kk][tx * 4];
            acc[0][0] = fmaf(a.x, b.x, acc[0][0]);
            acc[0][1] = fmaf(a.x, b.y, acc[0][1]);
            acc[0][2] = fmaf(a.x, b.z, acc[0][2]);
            acc[0][3] = fmaf(a.x, b.w, acc[0][3]);
            acc[1][0] = fmaf(a.y, b.x, acc[1][0]);
            acc[1][1] = fmaf(a.y, b.y, acc[1][1]);
            acc[1][2] = fmaf(a.y, b.z, acc[1][2]);
            acc[1][3] = fmaf(a.y, b.w, acc[1][3]);
            acc[2][0] = fmaf(a.z, b.x, acc[2][0]);
            acc[2][1] = fmaf(a.z, b.y, acc[2][1]);
            acc[2][2] = fmaf(a.z, b.z, acc[2][2]);
            acc[2][3] = fmaf(a.z, b.w, acc[2][3]);
            acc[3][0] = fmaf(a.w, b.x, acc[3][0]);
            acc[3][1] = fmaf(a.w, b.y, acc[3][1]);
            acc[3][2] = fmaf(a.w, b.z, acc[3][2]);
            acc[3][3] = fmaf(a.w, b.w, acc[3][3]);
        }
        __syncthreads();
    }
    float4 bb = *(const float4*)(bias + n0 + tx * 4);
#pragma unroll
    for (int i = 0; i < 4; i++) {
        int row = m0 + ty * 4 + i;
        if (row < M) {
            float4 o;
            o.x = acc[i][0] + bb.x;
            o.y = acc[i][1] + bb.y;
            o.z = acc[i][2] + bb.z;
            o.w = acc[i][3] + bb.w;
            *(float4*)(C + (long)row * N + n0 + tx * 4) = o;
        }
    }
}

// ---------------- GATv2 attention + aggregation (online softmax) -------------
// One warp handles a 256-channel block of one destination node.
// Each lane owns 8 contiguous channels; its 16x8 slice of We stays in registers.
// A head spans C/8 lanes (C=64 -> 8 lanes, C=128 -> 16 lanes); the logit
// reduction is a butterfly over exactly that lane group.
template<int HC, int C, bool CONCAT>
__global__ __launch_bounds__(256, 1)
void k_gat(const float* __restrict__ XL, const float* __restrict__ XR,
           const float* __restrict__ EA, const float* __restrict__ We,
           const float* __restrict__ att, const float* __restrict__ bias,
           const int* __restrict__ rowptr, const int* __restrict__ csrc,
           const int* __restrict__ ceid, float* __restrict__ Hout, int N)
{
    constexpr int WPN = HC / 256;   // warps per node
    constexpr int LPH = C / 8;      // lanes per head
    int gw = (blockIdx.x * (int)blockDim.x + (int)threadIdx.x) >> 5;
    int lane = threadIdx.x & 31;
    int n = gw / WPN;
    if (n >= N) return;
    int half = gw - n * WPN;
    int cbase = half * 256 + lane * 8;

    // register-resident We slice (16 x 8) and att slice (8)
    float w_r[16][8];
#pragma unroll
    for (int k = 0; k < 16; k++) {
        float4 a = *(const float4*)(We + k * HC + cbase);
        float4 b = *(const float4*)(We + k * HC + cbase + 4);
        w_r[k][0] = a.x; w_r[k][1] = a.y; w_r[k][2] = a.z; w_r[k][3] = a.w;
        w_r[k][4] = b.x; w_r[k][5] = b.y; w_r[k][6] = b.z; w_r[k][7] = b.w;
    }
    float att_r[8];
    {
        float4 a = *(const float4*)(att + cbase);
        float4 b = *(const float4*)(att + cbase + 4);
        att_r[0] = a.x; att_r[1] = a.y; att_r[2] = a.z; att_r[3] = a.w;
        att_r[4] = b.x; att_r[5] = b.y; att_r[6] = b.z; att_r[7] = b.w;
    }
    float xr_r[8];
    {
        const float* p = XR + (long)n * HC + cbase;
        float4 a = *(const float4*)p;
        float4 b = *(const float4*)(p + 4);
        xr_r[0] = a.x; xr_r[1] = a.y; xr_r[2] = a.z; xr_r[3] = a.w;
        xr_r[4] = b.x; xr_r[5] = b.y; xr_r[6] = b.z; xr_r[7] = b.w;
    }

    int e0 = rowptr[n], e1 = rowptr[n + 1];
    float m = -3.0e38f, s = 0.f;
    float acc[8];
#pragma unroll
    for (int j = 0; j < 8; j++) acc[j] = 0.f;

    for (int p = e0; p < e1; p++) {
        int src = csrc[p];
        int eid = ceid[p];
        float ea[16];
        {
            const float4* q = (const float4*)(EA + (long)eid * 16);
            float4 v0 = q[0], v1 = q[1], v2 = q[2], v3 = q[3];
            ea[0] = v0.x; ea[1] = v0.y; ea[2] = v0.z; ea[3] = v0.w;
            ea[4] = v1.x; ea[5] = v1.y; ea[6] = v1.z; ea[7] = v1.w;
            ea[8] = v2.x; ea[9] = v2.y; ea[10] = v2.z; ea[11] = v2.w;
            ea[12] = v3.x; ea[13] = v3.y; ea[14] = v3.z; ea[15] = v3.w;
        }
        float xl[8];
        {
            const float* q = XL + (long)src * HC + cbase;
            float4 a = *(const float4*)q;
            float4 b = *(const float4*)(q + 4);
            xl[0] = a.x; xl[1] = a.y; xl[2] = a.z; xl[3] = a.w;
            xl[4] = b.x; xl[5] = b.y; xl[6] = b.z; xl[7] = b.w;
        }
        float part = 0.f;
#pragma unroll
        for (int j = 0; j < 8; j++) {
            float ev = 0.f;
#pragma unroll
            for (int k = 0; k < 16; k++) ev = fmaf(ea[k], w_r[k][j], ev);
            float v = xl[j] + xr_r[j] + ev;
            float lr = fmaxf(v, 0.2f * v);   // leaky_relu(0.2)
            part = fmaf(att_r[j], lr, part);
        }
        // reduce the logit over all lanes of this head (LPH lanes)
#pragma unroll
        for (int off = 1; off < LPH; off <<= 1)
            part += __shfl_xor_sync(FULLMASK, part, off);
        // online softmax update (per head; lanes in a head group agree)
        if (part > m) {
            float sc = __expf(m - part);
            s *= sc;
#pragma unroll
            for (int j = 0; j < 8; j++) acc[j] *= sc;
            m = part;
        }
        float pe = __expf(part - m);
        s += pe;
#pragma unroll
        for (int j = 0; j < 8; j++) acc[j] = fmaf(pe, xl[j], acc[j]);
    }

    float inv = (e1 > e0) ? (1.f / s) : 0.f;
    if (CONCAT) {
        float4 b0 = *(const float4*)(bias + cbase);
        float4 b1 = *(const float4*)(bias + cbase + 4);
        float4 o0, o1;
        o0.x = fmaf(acc[0], inv, b0.x);
        o0.y = fmaf(acc[1], inv, b0.y);
        o0.z = fmaf(acc[2], inv, b0.z);
        o0.w = fmaf(acc[3], inv, b0.w);
        o1.x = fmaf(acc[4], inv, b1.x);
        o1.y = fmaf(acc[5], inv, b1.y);
        o1.z = fmaf(acc[6], inv, b1.z);
        o1.w = fmaf(acc[7], inv, b1.w);
        float* q = Hout + (long)n * HC + cbase;
        *(float4*)q = o0;
        *(float4*)(q + 4) = o1;
    } else {
        // mean over heads; Hout pre-initialized with bias.
        // This warp holds 2 heads (lanes 0-15 = head A, 16-31 = head B);
        // shfl 16 pairs matching channels of the two heads.
#pragma unroll
        for (int j = 0; j < 8; j++) {
            float r = acc[j] * inv;
            r += __shfl_xor_sync(FULLMASK, r, 16);
            if (lane < 16)
                atomicAdd(Hout + (long)n * C + (lane & 15) * 8 + j, 0.25f * r);
        }
    }
}

__global__ void k_init_bias(float* H, const float* __restrict__ bias, int total, int C) {
    int i = blockIdx.x * blockDim.x + threadIdx.x;
    if (i < total) H[i] = bias[i & (C - 1)];
}

// ---------------- pooling ----------------------------------------------------
__global__ void k_pool_init(float* out, int* gcnt) {
    int i = blockIdx.x * blockDim.x + threadIdx.x;
    if (i < NG * 256) out[i] = ((i & 255) < 128) ? -FLT_MAX : 0.f;
    if (i < NG) gcnt[i] = 0;
}

__global__ void k_pool_acc(const float* __restrict__ H, const int* __restrict__ batch,
                           float* out, int* gcnt) {
    int i = blockIdx.x * blockDim.x + threadIdx.x;
    if (i >= NN * 128) return;
    int nd = i >> 7, c = i & 127;
    int g = batch[nd];
    float v = H[i];
    float* mx = out + g * 256 + c;
    if (v >= 0.f) atomicMax((int*)mx, __float_as_int(v));
    else atomicMin((unsigned int*)mx, __float_as_uint(v));
    atomicAdd(out + g * 256 + 128 + c, v);
    if (c == 0) atomicAdd(&gcnt[g], 1);
}

__global__ void k_pool_fin(float* out, const int* __restrict__ gcnt) {
    int i = blockIdx.x * blockDim.x + threadIdx.x;
    if (i < NG * 128) {
        int g = i >> 7, c = i & 127;
        float cnt = (float)(gcnt[g] > 0 ? gcnt[g] : 1);
        out[g * 256 + 128 + c] /= cnt;
    }
}

// ---------------- launch -----------------------------------------------------
extern "C" void kernel_launch(void* const* d_in, const int* in_sizes, int n_in,
                              void* d_out, int out_size)
{
    const float* x     = (const float*)d_in[0];
    const float* ea    = (const float*)d_in[1];
    const int*   ei    = (const int*)d_in[2];
    const int*   batch = (const int*)d_in[3];
    const float* Wl[3] = {(const float*)d_in[4],  (const float*)d_in[11], (const float*)d_in[18]};
    const float* bl[3] = {(const float*)d_in[5],  (const float*)d_in[12], (const float*)d_in[19]};
    const float* Wr[3] = {(const float*)d_in[6],  (const float*)d_in[13], (const float*)d_in[20]};
    const float* br[3] = {(const float*)d_in[7],  (const float*)d_in[14], (const float*)d_in[21]};
    const float* We[3] = {(const float*)d_in[8],  (const float*)d_in[15], (const float*)d_in[22]};
    const float* At[3] = {(const float*)d_in[9],  (const float*)d_in[16], (const float*)d_in[23]};
    const float* Bi[3] = {(const float*)d_in[10], (const float*)d_in[17], (const float*)d_in[24]};
    float* out = (float*)d_out;

    float *XL, *XR, *HA, *HB;
    int *cnt, *rowptr, *cursor, *csrc, *ceid, *gcnt;
    cudaGetSymbolAddress((void**)&XL, g_XL);
    cudaGetSymbolAddress((void**)&XR, g_XR);
    cudaGetSymbolAddress((void**)&HA, g_HA);
    cudaGetSymbolAddress((void**)&HB, g_HB);
    cudaGetSymbolAddress((void**)&cnt, g_cnt);
    cudaGetSymbolAddress((void**)&rowptr, g_rowptr);
    cudaGetSymbolAddress((void**)&cursor, g_cursor);
    cudaGetSymbolAddress((void**)&csrc, g_csrc);
    cudaGetSymbolAddress((void**)&ceid, g_ceid);
    cudaGetSymbolAddress((void**)&gcnt, g_gcnt);

    // ---- CSR by destination ----
    k_zero_cnt<<<(NN + 255) / 256, 256>>>(cnt, NN);
    k_hist<<<(NE + 255) / 256, 256>>>(ei, cnt, NE);
    k_scan<<<1, 1024>>>(cnt, rowptr, cursor, NN);
    k_scatter<<<(NE + 255) / 256, 256>>>(ei, cursor, csrc, ceid, NE);

    const int MT = (NN + 63) / 64;  // 313

    // ---- layer 0: in x[20000,128] -> HA[20000,256] ----
    k_gemm_bias<<<dim3(4, MT), 256>>>(x, Wl[0], bl[0], XL, NN, 256, 128);
    k_gemm_bias<<<dim3(4, MT), 256>>>(x, Wr[0], br[0], XR, NN, 256, 128);
    k_gat<256, 64, true><<<(NN + 7) / 8, 256>>>(XL, XR, ea, We[0], At[0], Bi[0],
                                                rowptr, csrc, ceid, HA, NN);

    // ---- layer 1: HA[20000,256] -> HB[20000,256] ----
    k_gemm_bias<<<dim3(4, MT), 256>>>(HA, Wl[1], bl[1], XL, NN, 256, 256);
    k_gemm_bias<<<dim3(4, MT), 256>>>(HA, Wr[1], br[1], XR, NN, 256, 256);
    k_gat<256, 64, true><<<(NN + 7) / 8, 256>>>(XL, XR, ea, We[1], At[1], Bi[1],
                                                rowptr, csrc, ceid, HB, NN);

    // ---- layer 2: HB[20000,256] -> HA[20000,128] (mean over heads) ----
    k_gemm_bias<<<dim3(8, MT), 256>>>(HB, Wl[2], bl[2], XL, NN, 512, 256);
    k_gemm_bias<<<dim3(8, MT), 256>>>(HB, Wr[2], br[2], XR, NN, 512, 256);
    k_init_bias<<<(NN * 128 + 255) / 256, 256>>>(HA, Bi[2], NN * 128, 128);
    k_gat<512, 128, false><<<(2 * NN + 7) / 8, 256>>>(XL, XR, ea, We[2], At[2], Bi[2],
                                                      rowptr, csrc, ceid, HA, NN);

    // ---- pooling: [64, 256] = concat(max, mean) ----
    k_pool_init<<<64, 256>>>(out, gcnt);
    k_pool_acc<<<(NN * 128 + 255) / 256, 256>>>(HA, batch, out, gcnt);
    k_pool_fin<<<32, 256>>>(out, gcnt);
}

// round 3
// speedup vs baseline: 1.2142x; 1.2142x over previous
#include <cuda_runtime.h>
#include <float.h>
#include <math.h>

#define FULLMASK 0xffffffffu

typedef unsigned long long ull;

static const int NN = 20000;   // nodes
static const int NE = 640000;  // edges
static const int NG = 64;      // graphs

// ---------------- packed f32x2 helpers (Blackwell FFMA2 path) ----------------
__device__ __forceinline__ ull pack2(float x, float y) {
    ull r; asm("mov.b64 %0,{%1,%2};" : "=l"(r) : "f"(x), "f"(y)); return r;
}
__device__ __forceinline__ ull dup2(float x) { return pack2(x, x); }
__device__ __forceinline__ void unpack2(ull v, float& x, float& y) {
    asm("mov.b64 {%0,%1},%2;" : "=f"(x), "=f"(y) : "l"(v));
}
__device__ __forceinline__ void fma2(ull& d, ull a, ull b) {
    asm("fma.rn.f32x2 %0,%1,%2,%0;" : "+l"(d) : "l"(a), "l"(b));
}
__device__ __forceinline__ ull add2(ull a, ull b) {
    ull r; asm("add.rn.f32x2 %0,%1,%2;" : "=l"(r) : "l"(a), "l"(b)); return r;
}
__device__ __forceinline__ ull mul2(ull a, ull b) {
    ull r; asm("mul.rn.f32x2 %0,%1,%2;" : "=l"(r) : "l"(a), "l"(b)); return r;
}

// ---------------- scratch (static device allocations; sanctioned) ------------
__device__ float g_XL[20000 * 512];
__device__ float g_XR[20000 * 512];
__device__ float g_HA[20000 * 256];
__device__ float g_HB[20000 * 256];
__device__ int   g_cnt[20000];
__device__ int   g_rowptr[20001];
__device__ int   g_cursor[20000];
__device__ int   g_csrc[640000];
__device__ int   g_ceid[640000];
__device__ int   g_gcnt[64];

// ---------------- CSR build --------------------------------------------------
__global__ void k_zero_cnt(int* cnt, int n) {
    int i = blockIdx.x * blockDim.x + threadIdx.x;
    if (i < n) cnt[i] = 0;
}

__global__ void k_hist(const int* __restrict__ ei, int* cnt, int E) {
    int e = blockIdx.x * blockDim.x + threadIdx.x;
    if (e < E) atomicAdd(&cnt[ei[E + e]], 1);
}

// single-block warp-shfl scan over n counts -> rowptr (inclusive at i+1), cursor = exclusive
__global__ void k_scan(const int* __restrict__ cnt, int* rowptr, int* cursor, int n) {
    __shared__ int wsum[32];
    __shared__ int carry_s;
    int tid = threadIdx.x, lane = tid & 31, wid = tid >> 5;
    if (tid == 0) { carry_s = 0; rowptr[0] = 0; }
    __syncthreads();
    for (int base = 0; base < n; base += 1024) {
        int i = base + tid;
        int v = (i < n) ? cnt[i] : 0;
        int x = v;
#pragma unroll
        for (int off = 1; off < 32; off <<= 1) {
            int t = __shfl_up_sync(FULLMASK, x, off);
            if (lane >= off) x += t;
        }
        if (lane == 31) wsum[wid] = x;
        __syncthreads();
        if (wid == 0) {
            int w = wsum[lane];
#pragma unroll
            for (int off = 1; off < 32; off <<= 1) {
                int t = __shfl_up_sync(FULLMASK, w, off);
                if (lane >= off) w += t;
            }
            wsum[lane] = w;
        }
        __syncthreads();
        int incl = x + (wid > 0 ? wsum[wid - 1] : 0) + carry_s;
        if (i < n) { rowptr[i + 1] = incl; cursor[i] = incl - v; }
        __syncthreads();
        if (tid == 1023) carry_s = incl;
        __syncthreads();
    }
}

__global__ void k_scatter(const int* __restrict__ ei, int* cursor,
                          int* __restrict__ csrc, int* __restrict__ ceid, int E) {
    int e = blockIdx.x * blockDim.x + threadIdx.x;
    if (e < E) {
        int dst = ei[E + e];
        int p = atomicAdd(&cursor[dst], 1);
        csrc[p] = ei[e];
        ceid[p] = e;
    }
}

// ---------------- fp32 tiled GEMM (FFMA2 inner): C = A@B + bias --------------
// BM=BN=64, BK=16, 256 threads, 4x4 per thread via packed f32x2.
__global__ __launch_bounds__(256)
void k_gemm_bias(const float* __restrict__ A, const float* __restrict__ B,
                 const float* __restrict__ bias, float* __restrict__ C,
                 int M, int N, int K)
{
    __shared__ __align__(16) float As[16][68];
    __shared__ __align__(16) float Bs[16][64];
    const int t = threadIdx.x;
    const int m0 = blockIdx.y * 64;
    const int n0 = blockIdx.x * 64;
    const int tx = t & 15, ty = t >> 4;
    const int arow = t >> 2;
    const int acol = (t & 3) * 4;
    const int brow = t >> 4;
    const int bcol = (t & 15) * 4;

    ull c2[4][2];
#pragma unroll
    for (int i = 0; i < 4; i++) { c2[i][0] = 0ULL; c2[i][1] = 0ULL; }

    for (int k0 = 0; k0 < K; k0 += 16) {
        float4 av = make_float4(0.f, 0.f, 0.f, 0.f);
        if (m0 + arow < M)
            av = *(const float4*)(A + (long)(m0 + arow) * K + k0 + acol);
        As[acol + 0][arow] = av.x;
        As[acol + 1][arow] = av.y;
        As[acol + 2][arow] = av.z;
        As[acol + 3][arow] = av.w;
        float4 bv = *(const float4*)(B + (long)(k0 + brow) * N + n0 + bcol);
        *(float4*)&Bs[brow][bcol] = bv;
        __syncthreads();
#pragma unroll
        for (int kk = 0; kk < 16; kk++) {
            float4 a = *(const float4*)&As[kk][ty * 4];
            ulonglong2 bb = *(const ulonglong2*)&Bs[kk][tx * 4];
            ull a0 = dup2(a.x), a1 = dup2(a.y), a2 = dup2(a.z), a3 = dup2(a.w);
            fma2(c2[0][0], a0, bb.x); fma2(c2[0][1], a0, bb.y);
            fma2(c2[1][0], a1, bb.x); fma2(c2[1][1], a1, bb.y);
            fma2(c2[2][0], a2, bb.x); fma2(c2[2][1], a2, bb.y);
            fma2(c2[3][0], a3, bb.x); fma2(c2[3][1], a3, bb.y);
        }
        __syncthreads();
    }
    float4 bb = *(const float4*)(bias + n0 + tx * 4);
#pragma unroll
    for (int i = 0; i < 4; i++) {
        int row = m0 + ty * 4 + i;
        if (row < M) {
            float4 o;
            unpack2(c2[i][0], o.x, o.y);
            unpack2(c2[i][1], o.z, o.w);
            o.x += bb.x; o.y += bb.y; o.z += bb.z; o.w += bb.w;
            *(float4*)(C + (long)row * N + n0 + tx * 4) = o;
        }
    }
}

// ---------------- GATv2 attention + aggregation (online softmax) -------------
// One warp handles a 256-channel block of one destination node; lane owns 8
// contiguous channels; the 16x8 We slice lives in registers as 16x4 f32x2 pairs.
// Edge indices are batch-loaded 32 at a time (coalesced) and broadcast via shfl;
// next edge's ea/xl loads are issued before computing the current edge.
template<int HC, int C, bool CONCAT>
__global__ __launch_bounds__(256, 1)
void k_gat(const float* __restrict__ XL, const float* __restrict__ XR,
           const float* __restrict__ EA, const float* __restrict__ We,
           const float* __restrict__ att, const float* __restrict__ bias,
           const int* __restrict__ rowptr, const int* __restrict__ csrc,
           const int* __restrict__ ceid, float* __restrict__ Hout, int N)
{
    constexpr int WPN = HC / 256;   // warps per node
    constexpr int LPH = C / 8;      // lanes per head
    __shared__ float s_red[4][128]; // layer-2 head-mean exchange (nib x channel)

    int widx = threadIdx.x >> 5;
    int lane = threadIdx.x & 31;
    int gw = blockIdx.x * 8 + widx;
    int n = gw / WPN;               // grids sized exactly; no early return
    int half = gw - n * WPN;
    int cbase = half * 256 + lane * 8;

    // register-resident packed We slice (16 x 4 f32x2), att, xr
    ull w2[16][4];
#pragma unroll
    for (int k = 0; k < 16; k++) {
        const ulonglong2* q = (const ulonglong2*)(We + k * HC + cbase);
        ulonglong2 u0 = q[0], u1 = q[1];
        w2[k][0] = u0.x; w2[k][1] = u0.y; w2[k][2] = u1.x; w2[k][3] = u1.y;
    }
    float att_r[8];
    {
        float4 a = *(const float4*)(att + cbase);
        float4 b = *(const float4*)(att + cbase + 4);
        att_r[0] = a.x; att_r[1] = a.y; att_r[2] = a.z; att_r[3] = a.w;
        att_r[4] = b.x; att_r[5] = b.y; att_r[6] = b.z; att_r[7] = b.w;
    }
    ull xr2[4];
    {
        const ulonglong2* q = (const ulonglong2*)(XR + (long)n * HC + cbase);
        ulonglong2 u0 = q[0], u1 = q[1];
        xr2[0] = u0.x; xr2[1] = u0.y; xr2[2] = u1.x; xr2[3] = u1.y;
    }

    int e0 = rowptr[n], e1 = rowptr[n + 1];
    float m = -3.0e38f, s = 0.f;
    ull acc2[4] = {0ULL, 0ULL, 0ULL, 0ULL};

    for (int pb = e0; pb < e1; pb += 32) {
        int myp = pb + lane;
        int msrc = 0, meid = 0;
        if (myp < e1) { msrc = __ldg(&csrc[myp]); meid = __ldg(&ceid[myp]); }
        int cnt = min(32, e1 - pb);

        // prime edge 0 of the batch
        float4 cA, cB, cC, cD; ulonglong2 cx0, cx1;
        {
            int s0 = __shfl_sync(FULLMASK, msrc, 0);
            int id0 = __shfl_sync(FULLMASK, meid, 0);
            const float4* q = (const float4*)(EA + (long)id0 * 16);
            cA = q[0]; cB = q[1]; cC = q[2]; cD = q[3];
            const ulonglong2* xq = (const ulonglong2*)(XL + (long)s0 * HC + cbase);
            cx0 = xq[0]; cx1 = xq[1];
        }
        for (int i = 0; i < cnt; i++) {
            float4 uA = cA, uB = cB, uC = cC, uD = cD;
            ulonglong2 ux0 = cx0, ux1 = cx1;
            if (i + 1 < cnt) {  // prefetch next edge while computing this one
                int sn = __shfl_sync(FULLMASK, msrc, i + 1);
                int idn = __shfl_sync(FULLMASK, meid, i + 1);
                const float4* q = (const float4*)(EA + (long)idn * 16);
                cA = q[0]; cB = q[1]; cC = q[2]; cD = q[3];
                const ulonglong2* xq = (const ulonglong2*)(XL + (long)sn * HC + cbase);
                cx0 = xq[0]; cx1 = xq[1];
            }
            float ea[16] = {uA.x, uA.y, uA.z, uA.w, uB.x, uB.y, uB.z, uB.w,
                            uC.x, uC.y, uC.z, uC.w, uD.x, uD.y, uD.z, uD.w};
            ull xl2[4] = {ux0.x, ux0.y, ux1.x, ux1.y};

            ull v0 = add2(xl2[0], xr2[0]);
            ull v1 = add2(xl2[1], xr2[1]);
            ull v2 = add2(xl2[2], xr2[2]);
            ull v3 = add2(xl2[3], xr2[3]);
#pragma unroll
            for (int k = 0; k < 16; k++) {
                ull ak = dup2(ea[k]);
                fma2(v0, ak, w2[k][0]);
                fma2(v1, ak, w2[k][1]);
                fma2(v2, ak, w2[k][2]);
                fma2(v3, ak, w2[k][3]);
            }
            float f[8];
            unpack2(v0, f[0], f[1]); unpack2(v1, f[2], f[3]);
            unpack2(v2, f[4], f[5]); unpack2(v3, f[6], f[7]);
            float part = 0.f;
#pragma unroll
            for (int j = 0; j < 8; j++) {
                float vv = f[j];
                float lr = fmaxf(vv, 0.2f * vv);   // leaky_relu(0.2)
                part = fmaf(att_r[j], lr, part);
            }
#pragma unroll
            for (int off = 1; off < LPH; off <<= 1)
                part += __shfl_xor_sync(FULLMASK, part, off);

            if (part > m) {
                float sc = __expf(m - part);
                s *= sc;
                ull sc2 = dup2(sc);
#pragma unroll
                for (int j = 0; j < 4; j++) acc2[j] = mul2(acc2[j], sc2);
                m = part;
            }
            float pe = __expf(part - m);
            s += pe;
            ull pe2 = dup2(pe);
            fma2(acc2[0], pe2, xl2[0]);
            fma2(acc2[1], pe2, xl2[1]);
            fma2(acc2[2], pe2, xl2[2]);
            fma2(acc2[3], pe2, xl2[3]);
        }
    }

    float inv = (e1 > e0) ? (1.f / s) : 0.f;
    float r[8];
    unpack2(acc2[0], r[0], r[1]); unpack2(acc2[1], r[2], r[3]);
    unpack2(acc2[2], r[4], r[5]); unpack2(acc2[3], r[6], r[7]);

    if (CONCAT) {
        float4 b0 = *(const float4*)(bias + cbase);
        float4 b1 = *(const float4*)(bias + cbase + 4);
        float4 o0, o1;
        o0.x = fmaf(r[0], inv, b0.x); o0.y = fmaf(r[1], inv, b0.y);
        o0.z = fmaf(r[2], inv, b0.z); o0.w = fmaf(r[3], inv, b0.w);
        o1.x = fmaf(r[4], inv, b1.x); o1.y = fmaf(r[5], inv, b1.y);
        o1.z = fmaf(r[6], inv, b1.z); o1.w = fmaf(r[7], inv, b1.w);
        float* q = Hout + (long)n * HC + cbase;
        *(float4*)q = o0;
        *(float4*)(q + 4) = o1;
    } else {
        // mean over 4 heads. Warp holds heads {2*half, 2*half+1}; pair them via
        // shfl 16, then combine the two warps of this node through shared memory
        // (warps 2n, 2n+1 are adjacent in the same block).
#pragma unroll
        for (int j = 0; j < 8; j++) {
            r[j] *= inv;
            r[j] += __shfl_xor_sync(FULLMASK, r[j], 16);
        }
        int nib = widx >> 1;
        int c = (lane & 15) * 8;
        if (half == 0 && lane < 16) {
#pragma unroll
            for (int j = 0; j < 8; j++) s_red[nib][c + j] = r[j];
        }
        __syncthreads();
        if (half == 1 && lane < 16) {
            float* q = Hout + (long)n * C + c;
#pragma unroll
            for (int j = 0; j < 8; j++)
                q[j] = bias[c + j] + 0.25f * (r[j] + s_red[nib][c + j]);
        }
    }
}

// ---------------- pooling ----------------------------------------------------
__global__ void k_pool_init(float* out, int* gcnt) {
    int i = blockIdx.x * blockDim.x + threadIdx.x;
    if (i < NG * 256) out[i] = ((i & 255) < 128) ? -FLT_MAX : 0.f;
    if (i < NG) gcnt[i] = 0;
}

__global__ void k_pool_acc(const float* __restrict__ H, const int* __restrict__ batch,
                           float* out, int* gcnt) {
    int i = blockIdx.x * blockDim.x + threadIdx.x;
    if (i >= NN * 128) return;
    int nd = i >> 7, c = i & 127;
    int g = batch[nd];
    float v = H[i];
    float* mx = out + g * 256 + c;
    if (v >= 0.f) atomicMax((int*)mx, __float_as_int(v));
    else atomicMin((unsigned int*)mx, __float_as_uint(v));
    atomicAdd(out + g * 256 + 128 + c, v);
    if (c == 0) atomicAdd(&gcnt[g], 1);
}

__global__ void k_pool_fin(float* out, const int* __restrict__ gcnt) {
    int i = blockIdx.x * blockDim.x + threadIdx.x;
    if (i < NG * 128) {
        int g = i >> 7, c = i & 127;
        float cnt = (float)(gcnt[g] > 0 ? gcnt[g] : 1);
        out[g * 256 + 128 + c] /= cnt;
    }
}

// ---------------- launch -----------------------------------------------------
extern "C" void kernel_launch(void* const* d_in, const int* in_sizes, int n_in,
                              void* d_out, int out_size)
{
    const float* x     = (const float*)d_in[0];
    const float* ea    = (const float*)d_in[1];
    const int*   ei    = (const int*)d_in[2];
    const int*   batch = (const int*)d_in[3];
    const float* Wl[3] = {(const float*)d_in[4],  (const float*)d_in[11], (const float*)d_in[18]};
    const float* bl[3] = {(const float*)d_in[5],  (const float*)d_in[12], (const float*)d_in[19]};
    const float* Wr[3] = {(const float*)d_in[6],  (const float*)d_in[13], (const float*)d_in[20]};
    const float* br[3] = {(const float*)d_in[7],  (const float*)d_in[14], (const float*)d_in[21]};
    const float* We[3] = {(const float*)d_in[8],  (const float*)d_in[15], (const float*)d_in[22]};
    const float* At[3] = {(const float*)d_in[9],  (const float*)d_in[16], (const float*)d_in[23]};
    const float* Bi[3] = {(const float*)d_in[10], (const float*)d_in[17], (const float*)d_in[24]};
    float* out = (float*)d_out;

    float *XL, *XR, *HA, *HB;
    int *cnt, *rowptr, *cursor, *csrc, *ceid, *gcnt;
    cudaGetSymbolAddress((void**)&XL, g_XL);
    cudaGetSymbolAddress((void**)&XR, g_XR);
    cudaGetSymbolAddress((void**)&HA, g_HA);
    cudaGetSymbolAddress((void**)&HB, g_HB);
    cudaGetSymbolAddress((void**)&cnt, g_cnt);
    cudaGetSymbolAddress((void**)&rowptr, g_rowptr);
    cudaGetSymbolAddress((void**)&cursor, g_cursor);
    cudaGetSymbolAddress((void**)&csrc, g_csrc);
    cudaGetSymbolAddress((void**)&ceid, g_ceid);
    cudaGetSymbolAddress((void**)&gcnt, g_gcnt);

    // ---- CSR by destination ----
    k_zero_cnt<<<(NN + 255) / 256, 256>>>(cnt, NN);
    k_hist<<<(NE + 255) / 256, 256>>>(ei, cnt, NE);
    k_scan<<<1, 1024>>>(cnt, rowptr, cursor, NN);
    k_scatter<<<(NE + 255) / 256, 256>>>(ei, cursor, csrc, ceid, NE);

    const int MT = (NN + 63) / 64;  // 313

    // ---- layer 0: x[20000,128] -> HA[20000,256] ----
    k_gemm_bias<<<dim3(4, MT), 256>>>(x, Wl[0], bl[0], XL, NN, 256, 128);
    k_gemm_bias<<<dim3(4, MT), 256>>>(x, Wr[0], br[0], XR, NN, 256, 128);
    k_gat<256, 64, true><<<(NN + 7) / 8, 256>>>(XL, XR, ea, We[0], At[0], Bi[0],
                                                rowptr, csrc, ceid, HA, NN);

    // ---- layer 1: HA[20000,256] -> HB[20000,256] ----
    k_gemm_bias<<<dim3(4, MT), 256>>>(HA, Wl[1], bl[1], XL, NN, 256, 256);
    k_gemm_bias<<<dim3(4, MT), 256>>>(HA, Wr[1], br[1], XR, NN, 256, 256);
    k_gat<256, 64, true><<<(NN + 7) / 8, 256>>>(XL, XR, ea, We[1], At[1], Bi[1],
                                                rowptr, csrc, ceid, HB, NN);

    // ---- layer 2: HB[20000,256] -> HA[20000,128] (mean over heads) ----
    k_gemm_bias<<<dim3(8, MT), 256>>>(HB, Wl[2], bl[2], XL, NN, 512, 256);
    k_gemm_bias<<<dim3(8, MT), 256>>>(HB, Wr[2], br[2], XR, NN, 512, 256);
    k_gat<512, 128, false><<<(2 * NN + 7) / 8, 256>>>(XL, XR, ea, We[2], At[2], Bi[2],
                                                      rowptr, csrc, ceid, HA, NN);

    // ---- pooling: [64, 256] = concat(max, mean) ----
    k_pool_init<<<64, 256>>>(out, gcnt);
    k_pool_acc<<<(NN * 128 + 255) / 256, 256>>>(HA, batch, out, gcnt);
    k_pool_fin<<<32, 256>>>(out, gcnt);
}